// round 1
// baseline (speedup 1.0000x reference)
#include <cuda_runtime.h>
#include <cstdint>

// Round 0: HBM-bound streaming weighted-BCE mean reduction.
// 256 MB read -> predicted ~40-55 us on GB300.

__global__ void rw_zero_kernel(float* out) {
    if (threadIdx.x == 0) out[0] = 0.0f;
}

__device__ __forceinline__ float bce_w(float x, int h, int mid, float t) {
    float w = (h >= mid) ? 2.0f : 1.0f;
    float bce = fmaxf(x, 0.0f) - x * t + log1pf(__expf(-fabsf(x)));
    return bce * w;
}

__global__ __launch_bounds__(256, 4)
void rw_loss_kernel(const float4* __restrict__ x4,
                    const int4*  __restrict__ h4,
                    const int*   __restrict__ target_p,
                    const int*   __restrict__ H_p,
                    float*       __restrict__ out,
                    int nvec, float inv_n) {
    const float t   = (float)(*target_p);
    const int   mid = (*H_p) >> 1;

    float acc = 0.0f;
    const int stride = gridDim.x * blockDim.x;
    for (int i = blockIdx.x * blockDim.x + threadIdx.x; i < nvec; i += stride) {
        float4 xv = x4[i];
        int4   hv = h4[i];
        acc += bce_w(xv.x, hv.x, mid, t);
        acc += bce_w(xv.y, hv.y, mid, t);
        acc += bce_w(xv.z, hv.z, mid, t);
        acc += bce_w(xv.w, hv.w, mid, t);
    }

    // warp reduction
    #pragma unroll
    for (int off = 16; off > 0; off >>= 1)
        acc += __shfl_xor_sync(0xFFFFFFFF, acc, off);

    __shared__ float warp_sums[8];
    const int lane = threadIdx.x & 31;
    const int wid  = threadIdx.x >> 5;
    if (lane == 0) warp_sums[wid] = acc;
    __syncthreads();

    if (wid == 0) {
        float v = (lane < 8) ? warp_sums[lane] : 0.0f;
        #pragma unroll
        for (int off = 4; off > 0; off >>= 1)
            v += __shfl_xor_sync(0xFFFFFFFF, v, off);
        if (lane == 0)
            atomicAdd(out, v * inv_n);
    }
}

extern "C" void kernel_launch(void* const* d_in, const int* in_sizes, int n_in,
                              void* d_out, int out_size) {
    const float* x      = (const float*)d_in[0];   // d_out (logits), N fp32
    const int*   target = (const int*)d_in[1];     // scalar int
    const int*   hidx   = (const int*)d_in[2];     // height_indices, N int32
    const int*   Hp     = (const int*)d_in[3];     // scalar int
    float* out = (float*)d_out;

    const int n = in_sizes[0];
    const int nvec = n / 4;   // N = 33554432, divisible by 4
    const float inv_n = 1.0f / (float)n;

    rw_zero_kernel<<<1, 32>>>(out);

    const int threads = 256;
    const int blocks  = 592;  // 148 SMs * 4
    rw_loss_kernel<<<blocks, threads>>>(
        (const float4*)x, (const int4*)hidx, target, Hp, out, nvec, inv_n);
}

// round 2
// speedup vs baseline: 1.3363x; 1.3363x over previous
#include <cuda_runtime.h>
#include <cstdint>

// Round 1: raise MLP (unroll x2, batched loads), raise occupancy (6 CTAs/SM),
// cheap softplus (__logf(1+__expf(-|x|))), streaming loads.
// Predict DRAM 62.8% -> ~88%, dur 58.1 -> ~43us.

__global__ void rw_zero_kernel(float* out) {
    out[0] = 0.0f;
}

__device__ __forceinline__ float bce_w(float x, int h, int mid, float t) {
    float ax  = fabsf(x);
    float e   = __expf(-ax);
    float sp  = __logf(1.0f + e);             // log1p(exp(-|x|)), e in (0,1]
    float bce = fmaxf(x, 0.0f) - x * t + sp;
    return (h >= mid) ? (bce + bce) : bce;    // weight 2 or 1
}

__global__ __launch_bounds__(256, 6)
void rw_loss_kernel(const float4* __restrict__ x4,
                    const int4*  __restrict__ h4,
                    const int*   __restrict__ target_p,
                    const int*   __restrict__ H_p,
                    float*       __restrict__ out,
                    int nvec, float inv_n) {
    const float t   = (float)(*target_p);
    const int   mid = (*H_p) >> 1;

    const int stride = gridDim.x * blockDim.x;
    int i = blockIdx.x * blockDim.x + threadIdx.x;

    float acc = 0.0f;

    // Unroll x2: 4 independent 16B loads issued back-to-back -> deep MLP.
    for (; i + stride < nvec; i += 2 * stride) {
        float4 a0 = __ldcs(&x4[i]);
        int4   b0 = __ldcs(&h4[i]);
        float4 a1 = __ldcs(&x4[i + stride]);
        int4   b1 = __ldcs(&h4[i + stride]);

        acc += bce_w(a0.x, b0.x, mid, t);
        acc += bce_w(a0.y, b0.y, mid, t);
        acc += bce_w(a0.z, b0.z, mid, t);
        acc += bce_w(a0.w, b0.w, mid, t);
        acc += bce_w(a1.x, b1.x, mid, t);
        acc += bce_w(a1.y, b1.y, mid, t);
        acc += bce_w(a1.z, b1.z, mid, t);
        acc += bce_w(a1.w, b1.w, mid, t);
    }
    if (i < nvec) {  // at most one leftover per thread
        float4 a0 = __ldcs(&x4[i]);
        int4   b0 = __ldcs(&h4[i]);
        acc += bce_w(a0.x, b0.x, mid, t);
        acc += bce_w(a0.y, b0.y, mid, t);
        acc += bce_w(a0.z, b0.z, mid, t);
        acc += bce_w(a0.w, b0.w, mid, t);
    }

    // warp reduction
    #pragma unroll
    for (int off = 16; off > 0; off >>= 1)
        acc += __shfl_xor_sync(0xFFFFFFFF, acc, off);

    __shared__ float warp_sums[8];
    const int lane = threadIdx.x & 31;
    const int wid  = threadIdx.x >> 5;
    if (lane == 0) warp_sums[wid] = acc;
    __syncthreads();

    if (wid == 0) {
        float v = (lane < 8) ? warp_sums[lane] : 0.0f;
        #pragma unroll
        for (int off = 4; off > 0; off >>= 1)
            v += __shfl_xor_sync(0xFFFFFFFF, v, off);
        if (lane == 0)
            atomicAdd(out, v * inv_n);
    }
}

extern "C" void kernel_launch(void* const* d_in, const int* in_sizes, int n_in,
                              void* d_out, int out_size) {
    const float* x      = (const float*)d_in[0];   // logits, N fp32
    const int*   target = (const int*)d_in[1];     // scalar int
    const int*   hidx   = (const int*)d_in[2];     // height_indices, N int32
    const int*   Hp     = (const int*)d_in[3];     // scalar int
    float* out = (float*)d_out;

    const int n = in_sizes[0];
    const int nvec = n / 4;   // N divisible by 4
    const float inv_n = 1.0f / (float)n;

    rw_zero_kernel<<<1, 1>>>(out);

    const int threads = 256;
    const int blocks  = 888;  // 148 SMs * 6
    rw_loss_kernel<<<blocks, threads>>>(
        (const float4*)x, (const int4*)hidx, target, Hp, out, nvec, inv_n);
}